// round 17
// baseline (speedup 1.0000x reference)
#include <cuda_runtime.h>
#include <cuda_bf16.h>
#include <cstdint>

#define B_ 1024
#define T_ 256
#define H_ 512
#define S_ 64
#define KTOT 1536
#define NCH 24          // 1536 / 64 K-chunks
#define NSTG 4          // cp.async pipeline stages
#define STG_BYTES 18432 // (64*72 + 64*72) bf16

// Acat = [Ahi | Alo | Ahi], Wcat = [Whi | Whi | Wlo]  (bf16, K contiguous)
// => C = Ahi@Whi + Alo@Whi + Ahi@Wlo in fp32 accum (drops only lo*lo ~2^-18)
__device__ __align__(16) __nv_bfloat16 g_A[2][B_ * KTOT];   // ping-pong state
__device__ __align__(16) __nv_bfloat16 g_W[H_ * KTOT];

__device__ __forceinline__ uint32_t smem_u32(const void* p) {
    uint32_t a;
    asm("{ .reg .u64 t; cvta.to.shared.u64 t, %1; cvt.u32.u64 %0, t; }" : "=r"(a) : "l"(p));
    return a;
}

#define CP_ASYNC16(smem, gptr) \
    asm volatile("cp.async.cg.shared.global [%0], [%1], 16;" :: "r"(smem), "l"(gptr))
#define CP_COMMIT() asm volatile("cp.async.commit_group;" ::: "memory")
#define CP_WAIT2()  asm volatile("cp.async.wait_group 2;" ::: "memory")
#define CP_WAIT0()  asm volatile("cp.async.wait_group 0;" ::: "memory")

#define LDSM4(r0, r1, r2, r3, addr)                                            \
    asm volatile("ldmatrix.sync.aligned.m8n8.x4.shared.b16 {%0,%1,%2,%3}, [%4];" \
                 : "=r"(r0), "=r"(r1), "=r"(r2), "=r"(r3) : "r"(addr))

#define MMA16816(c, a0, a1, a2, a3, b0, b1)                                    \
    asm volatile("mma.sync.aligned.m16n8k16.row.col.f32.bf16.bf16.f32 "        \
                 "{%0,%1,%2,%3},{%4,%5,%6,%7},{%8,%9},{%0,%1,%2,%3};"          \
                 : "+f"((c)[0]), "+f"((c)[1]), "+f"((c)[2]), "+f"((c)[3])      \
                 : "r"(a0), "r"(a1), "r"(a2), "r"(a3), "r"(b0), "r"(b1))

// ---------------- prep kernels ----------------
__global__ void wsplit(const float* __restrict__ W) {
    int idx = blockIdx.x * 256 + threadIdx.x;    // n*512 + k
    int n = idx >> 9, k = idx & 511;
    float v = W[idx];
    __nv_bfloat16 h = __float2bfloat16(v);
    __nv_bfloat16 l = __float2bfloat16(v - __bfloat162float(h));
    __nv_bfloat16* p = g_W + n * KTOT;
    p[k] = h; p[512 + k] = h; p[1024 + k] = l;
}

__global__ void rnn_first(const float* __restrict__ x, const float* __restrict__ w_in,
                          const float* __restrict__ b_ih, const float* __restrict__ b_hh) {
    int idx = blockIdx.x * 256 + threadIdx.x;    // b*512 + i
    int b = idx >> 9, i = idx & 511;
    float v = fmaxf(x[b * T_] * w_in[i] + b_ih[i] + b_hh[i], 0.0f);
    __nv_bfloat16 h = __float2bfloat16(v);
    __nv_bfloat16 l = __float2bfloat16(v - __bfloat162float(h));
    __nv_bfloat16* p = g_A[0] + b * KTOT;
    p[i] = h; p[512 + i] = l; p[1024 + i] = h;
}

// final y (s = S-1 only): y[b] = h[b,:].w_fc + b_fc
__global__ void ykern(int ping, const float* __restrict__ w_fc, const float* __restrict__ b_fc,
                      float* __restrict__ out, int s) {
    int w = blockIdx.x * 8 + (threadIdx.x >> 5);
    int lane = threadIdx.x & 31;
    const __nv_bfloat16* p = g_A[ping] + w * KTOT;
    float acc = 0.0f;
#pragma unroll
    for (int k = lane; k < 512; k += 32)
        acc += (__bfloat162float(p[k]) + __bfloat162float(p[512 + k])) * w_fc[k];
#pragma unroll
    for (int o = 16; o; o >>= 1) acc += __shfl_xor_sync(0xFFFFFFFFu, acc, o);
    if (lane == 0) out[w * S_ + s] = acc + b_fc[0];
}

// ---------------- tensor-core step kernel ----------------
// Grid (16,8): CTA tile 64(b) x 64(i); 512 threads / 16 warps, warp tile 16x16.
// 4-stage cp.async pipeline, K=1536 in chunks of 64, ONE barrier per chunk.
// R=true: y for this CTA's 64 rows computed up front into s_y (fused ykern),
//         out written by blockIdx.y==0; t carries the rollout step index s.
template <bool R>
__global__ __launch_bounds__(512) void rnn_step(
    int ping, const float* __restrict__ w_in, const float* __restrict__ b_ih,
    const float* __restrict__ b_hh, const float* __restrict__ x, int t,
    const float* __restrict__ w_fc, const float* __restrict__ b_fc,
    float* __restrict__ out)
{
    extern __shared__ char sm[];                 // NSTG * STG_BYTES
    __shared__ float s_w[64], s_b[64], s_y[64];

    const int tid = threadIdx.x;
    const int lane = tid & 31, w = tid >> 5;
    const int wm = w & 3;          // m tile (16 rows)
    const int wn = w >> 2;         // n tile (16 cols)
    const int m0 = blockIdx.x * 64, n0 = blockIdx.y * 64;

    if (tid < 64) {
        s_w[tid] = w_in[n0 + tid];
        s_b[tid] = b_ih[n0 + tid] + b_hh[n0 + tid];
    }

    const char* gA = (const char*)(g_A[ping]);
    const char* gW = (const char*)g_W;
    const uint32_t smb = smem_u32(sm);

    // loader: 512 threads, 1 A-unit + 1 W-unit (16B) per thread per stage
    const int lr = tid >> 3, lu = tid & 7;       // row 0..63, unit 0..7
    const char* gAp = gA + (long)(m0 + lr) * 3072 + lu * 16;
    const char* gWp = gW + (long)(n0 + lr) * 3072 + lu * 16;
    const uint32_t sA1 = smb + lr * 144 + lu * 16;
    const uint32_t sW1 = sA1 + 9216;

    // prologue: stages 0..2 in flight
#pragma unroll
    for (int s = 0; s < 3; ++s) {
        const uint32_t so = s * STG_BYTES;
        const int go = s * 128;
        CP_ASYNC16(sA1 + so, gAp + go);
        CP_ASYNC16(sW1 + so, gWp + go);
        CP_COMMIT();
    }

    // fused y for rollout: 8 threads per row, 64 elems each, shfl-reduce
    if (R) {
        const int row = tid >> 3, seg = (tid & 7) * 64;
        const __nv_bfloat16* p = g_A[ping] + (long)(m0 + row) * KTOT;
        float acc = 0.0f;
#pragma unroll 16
        for (int k = 0; k < 64; ++k) {
            int kk = seg + k;
            acc += (__bfloat162float(p[kk]) + __bfloat162float(p[512 + kk])) * w_fc[kk];
        }
        acc += __shfl_xor_sync(0xFFFFFFFFu, acc, 4);
        acc += __shfl_xor_sync(0xFFFFFFFFu, acc, 2);
        acc += __shfl_xor_sync(0xFFFFFFFFu, acc, 1);
        if ((tid & 7) == 0) {
            float y = acc + b_fc[0];
            s_y[row] = y;
            if (blockIdx.y == 0) out[(m0 + row) * S_ + t] = y;
        }
    }

    float acc[2][4];
#pragma unroll
    for (int b = 0; b < 2; ++b)
#pragma unroll
        for (int c = 0; c < 4; ++c) acc[b][c] = 0.0f;

    // fragment addresses (verified maps, warp tile 16x16)
    const uint32_t aoff = ((wm * 16 + (lane & 15)) * 72 + (lane >> 4) * 8) * 2;
    const uint32_t boff = 9216 +
        ((wn * 16 + ((lane >> 4) << 3) + (lane & 7)) * 72 + ((lane >> 3) & 1) * 8) * 2;

    for (int c = 0; c < NCH; ++c) {
        CP_WAIT2();
        __syncthreads();   // stage c&3 ready AND everyone done reading stage (c-1)&3
        if (c + 3 < NCH) {
            const uint32_t so = ((c + 3) & 3) * STG_BYTES;
            const int go = (c + 3) * 128;
            CP_ASYNC16(sA1 + so, gAp + go);
            CP_ASYNC16(sW1 + so, gWp + go);
        }
        CP_COMMIT();

        const uint32_t sb = (c & 3) * STG_BYTES;
        const uint32_t ab = smb + sb + aoff;
        const uint32_t bb = smb + sb + boff;
#pragma unroll
        for (int kk = 0; kk < 4; ++kk) {
            uint32_t af[4], bf[4];
            LDSM4(af[0], af[1], af[2], af[3], ab + kk * 32);
            LDSM4(bf[0], bf[1], bf[2], bf[3], bb + kk * 32);
            MMA16816(acc[0], af[0], af[1], af[2], af[3], bf[0], bf[1]);
            MMA16816(acc[1], af[0], af[1], af[2], af[3], bf[2], bf[3]);
        }
    }
    CP_WAIT0();
    __syncthreads();       // also orders s_y before epilogue reads

    // epilogue: rows rb, rb+8 of warp m-tile; cols 2*(lane&3) of each n8 tile
    const int rb = lane >> 2;
    float xv[2];
    {
        int r0 = wm * 16 + rb;
        if (R) { xv[0] = s_y[r0]; xv[1] = s_y[r0 + 8]; }
        else   { xv[0] = x[(m0 + r0) * T_ + t]; xv[1] = x[(m0 + r0 + 8) * T_ + t]; }
    }

    __nv_bfloat16* outA = g_A[ping ^ 1];
#pragma unroll
    for (int nq = 0; nq < 2; ++nq) {
        const int iloc = wn * 16 + nq * 8 + 2 * (lane & 3);
        const int gi = n0 + iloc;
        const float w0 = s_w[iloc], w1 = s_w[iloc + 1];
        const float bb0 = s_b[iloc], bb1 = s_b[iloc + 1];
#pragma unroll
        for (int hh = 0; hh < 2; ++hh) {
            float v0 = fmaxf(acc[nq][hh * 2 + 0] + xv[hh] * w0 + bb0, 0.0f);
            float v1 = fmaxf(acc[nq][hh * 2 + 1] + xv[hh] * w1 + bb1, 0.0f);
            __nv_bfloat16 h0 = __float2bfloat16(v0), h1 = __float2bfloat16(v1);
            __nv_bfloat16 l0 = __float2bfloat16(v0 - __bfloat162float(h0));
            __nv_bfloat16 l1 = __float2bfloat16(v1 - __bfloat162float(h1));
            __nv_bfloat162 hp; hp.x = h0; hp.y = h1;
            __nv_bfloat162 lp; lp.x = l0; lp.y = l1;
            uint32_t hu = *(uint32_t*)&hp, lu2 = *(uint32_t*)&lp;
            const int b = m0 + wm * 16 + rb + hh * 8;
            __nv_bfloat16* p = outA + (long)b * KTOT;
            *(uint32_t*)(p + gi)        = hu;    // Ahi
            *(uint32_t*)(p + 512 + gi)  = lu2;   // Alo
            *(uint32_t*)(p + 1024 + gi) = hu;    // Ahi duplicate
        }
    }
}

// ---------------- launch ----------------
extern "C" void kernel_launch(void* const* d_in, const int* in_sizes, int n_in,
                              void* d_out, int out_size) {
    // metadata order: x, W_ih, W_hh, b_ih, b_hh, W_fc, b_fc, num_steps
    const float* x    = (const float*)d_in[0];
    const float* W_ih = (const float*)d_in[1];   // (H,1) contiguous = w_in
    const float* W_hh = (const float*)d_in[2];
    const float* b_ih = (const float*)d_in[3];
    const float* b_hh = (const float*)d_in[4];
    const float* W_fc = (const float*)d_in[5];   // (1,H) contiguous
    const float* b_fc = (const float*)d_in[6];
    float* out = (float*)d_out;                  // (B, 64, 1) float32
    (void)in_sizes; (void)n_in; (void)out_size;

    const int smem = NSTG * STG_BYTES;           // 73728
    cudaFuncSetAttribute(rnn_step<false>, cudaFuncAttributeMaxDynamicSharedMemorySize, smem);
    cudaFuncSetAttribute(rnn_step<true>,  cudaFuncAttributeMaxDynamicSharedMemorySize, smem);

    wsplit<<<(H_ * H_) / 256, 256>>>(W_hh);
    rnn_first<<<(B_ * H_) / 256, 256>>>(x, W_ih, b_ih, b_hh);

    dim3 grid(16, 8);   // 128 CTAs, 64x64 tiles
    int ping = 0;
    for (int t = 1; t < T_; ++t) {
        rnn_step<false><<<grid, 512, smem>>>(ping, W_ih, b_ih, b_hh, x, t,
                                             nullptr, nullptr, nullptr);
        ping ^= 1;
    }
    // rollout s = 0..62 fused (y_s + out + h_{s+1}); s = 63 needs only y
    for (int s = 0; s < S_ - 1; ++s) {
        rnn_step<true><<<grid, 512, smem>>>(ping, W_ih, b_ih, b_hh, nullptr, s,
                                            W_fc, b_fc, out);
        ping ^= 1;
    }
    ykern<<<128, 256>>>(ping, W_fc, b_fc, out, S_ - 1);
}